// round 9
// baseline (speedup 1.0000x reference)
#include <cuda_runtime.h>
#include <cstdint>

#define N_TOK 32768
#define DDIM 256
#define KSTAGES 8
#define CDSZ 1024

#define TM 48
#define TN 256
#define TKC 16
#define AS_STRIDE 264
#define NBLK ((N_TOK + TM - 1) / TM)      // 683 (last tile partial)
#define BS_F4 (TKC * 4 * 16)              // 1024 float4
#define SMEM_BYTES (TM * AS_STRIDE * 4 + BS_F4 * 16)   // 50688 + 16384 = 67072

typedef unsigned long long u64;

// ------------------------- device scratch (no allocs) -------------------------
__device__ float g_res[N_TOK * DDIM];               // running residual (32 MB)
__device__ float g_cbT[KSTAGES * DDIM * CDSZ];      // d-major codebooks (8 MB)
__device__ float g_cnorm[KSTAGES * CDSZ];           // ||c||^2
__device__ float g_partials[KSTAGES * NBLK];        // per-block loss partials

__device__ __forceinline__ u64 pack2(float x, float y) {
    u64 r; asm("mov.b64 %0, {%1, %2};" : "=l"(r) : "f"(x), "f"(y)); return r;
}
__device__ __forceinline__ float2 unpack2(u64 v) {
    float2 f; asm("mov.b64 {%0, %1}, %2;" : "=f"(f.x), "=f"(f.y) : "l"(v)); return f;
}
__device__ __forceinline__ u64 fma2(u64 a, u64 b, u64 c) {
    u64 d; asm("fma.rn.f32x2 %0, %1, %2, %3;" : "=l"(d) : "l"(a), "l"(b), "l"(c)); return d;
}
__device__ __forceinline__ uint32_t smem_u32(const void* p) {
    uint32_t a;
    asm("{ .reg .u64 t; cvta.to.shared.u64 t, %1; cvt.u32.u64 %0, t; }" : "=r"(a) : "l"(p));
    return a;
}
#define CP_ASYNC16(s, g) \
    asm volatile("cp.async.cg.shared.global [%0], [%1], 16;" :: "r"(s), "l"(g) : "memory")
#define CP_COMMIT() asm volatile("cp.async.commit_group;" ::: "memory")

// ------------------------- prep: transpose + code norms -------------------------
__global__ void transpose_cb_kernel(const float* __restrict__ cb) {
    __shared__ float tile[32][33];
    int s = blockIdx.z;
    int d0 = blockIdx.x * 32, c0 = blockIdx.y * 32;
    int tx = threadIdx.x, ty = threadIdx.y;
    const float* src = cb + (size_t)s * CDSZ * DDIM;
    float* dst = g_cbT + (size_t)s * DDIM * CDSZ;
#pragma unroll
    for (int i = 0; i < 32; i += 8)
        tile[ty + i][tx] = src[(size_t)(c0 + ty + i) * DDIM + d0 + tx];
    __syncthreads();
#pragma unroll
    for (int i = 0; i < 32; i += 8)
        dst[(size_t)(d0 + ty + i) * CDSZ + c0 + tx] = tile[tx][ty + i];
}

__global__ void cnorm_kernel(const float* __restrict__ cb) {
    int row = blockIdx.x * 8 + (threadIdx.x >> 5);
    int lane = threadIdx.x & 31;
    const float* p = cb + (size_t)row * DDIM;
    float s = 0.f;
#pragma unroll
    for (int j = 0; j < 8; j++) { float v = p[lane + 32 * j]; s = fmaf(v, v, s); }
#pragma unroll
    for (int off = 16; off; off >>= 1) s += __shfl_xor_sync(0xffffffffu, s, off);
    if (lane == 0) g_cnorm[row] = s;
}

// ------------------------- per-stage fused GEMM+argmin+update -------------------------
extern __shared__ float smem_dyn[];

__global__ __launch_bounds__(128, 3) void rvq_stage_kernel(
    const float* __restrict__ x,
    const float* __restrict__ cb,    // this stage's codebook [CDSZ*DDIM], c-major
    int stage,
    float* __restrict__ encf)
{
    float* As = smem_dyn;                                   // [TM][AS_STRIDE]
    float4* Bs4 = (float4*)(smem_dyn + TM * AS_STRIDE);     // [16 k][4 q][16] float4 (q-rotated)
    __shared__ float rnorm_s[TM];
    __shared__ int bestI_s[TM];
    __shared__ float wsum[4];

    const int tid = threadIdx.x;
    const int tx = tid & 15, ty = tid >> 4;                 // tx: 16 code groups, ty: 8 token groups
    const int tok0 = blockIdx.x * TM;
    const float* cbT = g_cbT + (size_t)stage * DDIM * CDSZ;
    const float* cnorm = g_cnorm + stage * CDSZ;
    const float* src = (stage == 0) ? x : g_res;
    const uint32_t sB = smem_u32(Bs4);

    // load 48x256 residual tile (float4, coalesced), zero-pad beyond N_TOK
#pragma unroll
    for (int it = 0; it < 24; it++) {
        int idx4 = it * 128 + tid;
        int r = idx4 >> 6;
        int c4 = (idx4 & 63) << 2;
        float4 v = make_float4(0.f, 0.f, 0.f, 0.f);
        if (tok0 + r < N_TOK)
            v = *(const float4*)&src[(size_t)(tok0 + r) * DDIM + c4];
        *(float4*)&As[r * AS_STRIDE + c4] = v;
    }
    __syncthreads();

    // rnorm per token (identical reduction order — bit-exact)
    {
        const int warpId = tid >> 5, lane = tid & 31;
        for (int t = warpId; t < TM; t += 4) {
            float s = 0.f;
#pragma unroll
            for (int j = 0; j < 8; j++) {
                float v = As[t * AS_STRIDE + lane + 32 * j];
                s = fmaf(v, v, s);
            }
#pragma unroll
            for (int off = 16; off; off >>= 1) s += __shfl_xor_sync(0xffffffffu, s, off);
            if (lane == 0) rnorm_s[t] = s;
        }
    }

    float bestVr[6];
    int bestIr[6];
#pragma unroll
    for (int i = 0; i < 6; i++) { bestVr[i] = 3.4e38f; bestIr[i] = 0; }

    for (int ct = 0; ct < CDSZ; ct += TN) {
        // pure dot accumulators: 6 tokens x 16 codes, k ascending 0..255 (bit-exact)
        u64 acc[6][8];
#pragma unroll
        for (int i = 0; i < 6; i++)
#pragma unroll
            for (int j = 0; j < 8; j++) acc[i][j] = 0ull;

        for (int kk = 0; kk < DDIM; kk += TKC) {
            __syncthreads();   // readers done with Bs
            // async-load B slice: 16 k x 256 codes, q-major with XOR rotation
#pragma unroll
            for (int it = 0; it < 8; it++) {
                int g = it * 128 + tid;          // 0..1023 float4 granules
                int k = g >> 6;                  // 0..15
                int rem = g & 63;
                int txg = rem >> 2, q = rem & 3;
                uint32_t dst = sB + (uint32_t)(((k * 4 + q) * 16 + ((txg + 4 * q) & 15)) * 16);
                CP_ASYNC16(dst, &cbT[(size_t)(kk + k) * CDSZ + ct + rem * 4]);
            }
            CP_COMMIT();
            asm volatile("cp.async.wait_group 0;" ::: "memory");
            __syncthreads();   // publish Bs

#pragma unroll
            for (int k4 = 0; k4 < TKC; k4 += 4) {
                float4 a4[6];
#pragma unroll
                for (int i = 0; i < 6; i++)
                    a4[i] = *(const float4*)&As[(ty * 6 + i) * AS_STRIDE + kk + k4];
#pragma unroll
                for (int dk = 0; dk < 4; dk++) {
                    const ulonglong2* bp = (const ulonglong2*)(Bs4 + (k4 + dk) * 64);
                    ulonglong2 B0 = bp[tx];
                    ulonglong2 B1 = bp[16 + ((tx + 4) & 15)];
                    ulonglong2 B2 = bp[32 + ((tx + 8) & 15)];
                    ulonglong2 B3 = bp[48 + ((tx + 12) & 15)];
#pragma unroll
                    for (int i = 0; i < 6; i++) {
                        float av = ((const float*)&a4[i])[dk];
                        u64 ap = pack2(av, av);
                        acc[i][0] = fma2(ap, B0.x, acc[i][0]);
                        acc[i][1] = fma2(ap, B0.y, acc[i][1]);
                        acc[i][2] = fma2(ap, B1.x, acc[i][2]);
                        acc[i][3] = fma2(ap, B1.y, acc[i][3]);
                        acc[i][4] = fma2(ap, B2.x, acc[i][4]);
                        acc[i][5] = fma2(ap, B2.y, acc[i][5]);
                        acc[i][6] = fma2(ap, B3.x, acc[i][6]);
                        acc[i][7] = fma2(ap, B3.y, acc[i][7]);
                    }
                }
            }
        }

        // d2 = (rnorm - 2*dot) + cnorm, explicit order; strict-< lowest-index argmin
        float2 cnp[8];
#pragma unroll
        for (int j = 0; j < 8; j++)
            cnp[j] = *(const float2*)&cnorm[ct + tx * 16 + j * 2];

#pragma unroll
        for (int i = 0; i < 6; i++) {
            float R = rnorm_s[ty * 6 + i];
            float bv = 3.4e38f; int bi = 0;
#pragma unroll
            for (int j = 0; j < 8; j++) {
                float2 f = unpack2(acc[i][j]);
                int c0 = ct + tx * 16 + j * 2;
                float d2x = __fadd_rn(__fsub_rn(R, __fmul_rn(2.0f, f.x)), cnp[j].x);
                float d2y = __fadd_rn(__fsub_rn(R, __fmul_rn(2.0f, f.y)), cnp[j].y);
                if (d2x < bv) { bv = d2x; bi = c0; }
                if (d2y < bv) { bv = d2y; bi = c0 + 1; }
            }
#pragma unroll
            for (int off = 8; off; off >>= 1) {
                float ov = __shfl_xor_sync(0xffffffffu, bv, off);
                int oi = __shfl_xor_sync(0xffffffffu, bi, off);
                if (ov < bv || (ov == bv && oi < bi)) { bv = ov; bi = oi; }
            }
            if (bv < bestVr[i]) { bestVr[i] = bv; bestIr[i] = bi; }
        }
    }
    if (tx == 0) {
#pragma unroll
        for (int i = 0; i < 6; i++) bestI_s[ty * 6 + i] = bestIr[i];
    }
    __syncthreads();

    // residual update + deterministic loss partial + enc output (proven chain)
    const int warpId = tid >> 5, lane = tid & 31;
    float lsum = 0.f;
    for (int t = warpId; t < TM; t += 4) {
        int token = tok0 + t;
        if (token >= N_TOK) break;
        int e = bestI_s[t];
        const float* crow = cb + (size_t)e * DDIM;
#pragma unroll
        for (int jj = 0; jj < 8; jj++) {
            int d = lane + jj * 32;
            float r = As[t * AS_STRIDE + d];
            float c = __ldg(&crow[d]);
            float nr = r - c;
            g_res[(size_t)token * DDIM + d] = nr;
            lsum = fmaf(nr, nr, lsum);
        }
        if (lane == 0) encf[(size_t)token * KSTAGES + stage] = (float)e;
    }
#pragma unroll
    for (int off = 16; off; off >>= 1) lsum += __shfl_xor_sync(0xffffffffu, lsum, off);
    if (lane == 0) wsum[warpId] = lsum;
    __syncthreads();
    if (tid == 0)
        g_partials[stage * NBLK + blockIdx.x] = wsum[0] + wsum[1] + wsum[2] + wsum[3];
}

// ------------------------- epilogue -------------------------
__global__ void finalize_kernel(float* __restrict__ out) {
    __shared__ float sh[256];
    int tid = threadIdx.x;
    float s = 0.f;
    for (int i = tid; i < KSTAGES * NBLK; i += 256) s += g_partials[i];
    sh[tid] = s;
    __syncthreads();
    for (int off = 128; off; off >>= 1) {
        if (tid < off) sh[tid] += sh[tid + off];
        __syncthreads();
    }
    if (tid == 0) {
        float loss = sh[0] * (1.0f / (float)((size_t)N_TOK * DDIM));
        out[0] = loss;   // loss_cd
        out[1] = loss;   // loss_enc
    }
}

__global__ void quant_kernel(const float* __restrict__ x, float* __restrict__ out) {
    float* q = out + 2 + (size_t)N_TOK * KSTAGES;
    int i = blockIdx.x * blockDim.x + threadIdx.x;
    int stride = gridDim.x * blockDim.x;
    for (; i < N_TOK * DDIM; i += stride) q[i] = x[i] - g_res[i];
}

// ------------------------- launch -------------------------
extern "C" void kernel_launch(void* const* d_in, const int* in_sizes, int n_in,
                              void* d_out, int out_size) {
    const float* x  = (const float*)d_in[0];
    const float* cb = (const float*)d_in[1];
    if (n_in >= 2 && in_sizes[0] == KSTAGES * CDSZ * DDIM && in_sizes[1] == N_TOK * DDIM) {
        const float* t = x; x = cb; cb = t;
    }
    float* out = (float*)d_out;

    cudaFuncSetAttribute(rvq_stage_kernel,
                         cudaFuncAttributeMaxDynamicSharedMemorySize, SMEM_BYTES);

    transpose_cb_kernel<<<dim3(8, 32, 8), dim3(32, 8)>>>(cb);
    cnorm_kernel<<<(KSTAGES * CDSZ) / 8, 256>>>(cb);

    for (int s = 0; s < KSTAGES; s++) {
        rvq_stage_kernel<<<NBLK, 128, SMEM_BYTES>>>(
            x, cb + (size_t)s * CDSZ * DDIM, s, out + 2);
    }

    finalize_kernel<<<1, 256>>>(out);
    quant_kernel<<<4096, 256>>>(x, out);
}

// round 10
// speedup vs baseline: 1.1662x; 1.1662x over previous
#include <cuda_runtime.h>
#include <cstdint>

#define N_TOK 32768
#define DDIM 256
#define KSTAGES 8
#define CDSZ 1024

#define TM 64
#define TN 256
#define TKC 16
#define AS_STRIDE 264
#define NTILE (N_TOK / TM)               // 512
#define NUNITS (KSTAGES * NTILE)         // 4096
#define GRID_P 296                        // 2 CTAs/SM x 148 SMs
#define BS_F4 (TKC * 4 * 16)             // 1024 float4 per buffer
#define SMEM_BYTES (TM * AS_STRIDE * 4 + 2 * BS_F4 * 16)  // 67584+32768=100352

typedef unsigned long long u64;

// ------------------------- device scratch (no allocs) -------------------------
__device__ float g_res[N_TOK * DDIM];
__device__ float g_cbT[KSTAGES * DDIM * CDSZ];
__device__ float g_cnorm[KSTAGES * CDSZ];
__device__ float g_partials[NUNITS];
__device__ int g_ticket;
__device__ int g_done[NTILE];

__device__ __forceinline__ u64 pack2(float x, float y) {
    u64 r; asm("mov.b64 %0, {%1, %2};" : "=l"(r) : "f"(x), "f"(y)); return r;
}
__device__ __forceinline__ float2 unpack2(u64 v) {
    float2 f; asm("mov.b64 {%0, %1}, %2;" : "=f"(f.x), "=f"(f.y) : "l"(v)); return f;
}
__device__ __forceinline__ u64 fma2(u64 a, u64 b, u64 c) {
    u64 d; asm("fma.rn.f32x2 %0, %1, %2, %3;" : "=l"(d) : "l"(a), "l"(b), "l"(c)); return d;
}
__device__ __forceinline__ uint32_t smem_u32(const void* p) {
    uint32_t a;
    asm("{ .reg .u64 t; cvta.to.shared.u64 t, %1; cvt.u32.u64 %0, t; }" : "=r"(a) : "l"(p));
    return a;
}
__device__ __forceinline__ int ld_acquire(const int* p) {
    int v; asm volatile("ld.global.acquire.gpu.b32 %0, [%1];" : "=r"(v) : "l"(p) : "memory");
    return v;
}
__device__ __forceinline__ void st_release(int* p, int v) {
    asm volatile("st.global.release.gpu.b32 [%0], %1;" :: "l"(p), "r"(v) : "memory");
}
#define CP_ASYNC16(s, g) \
    asm volatile("cp.async.cg.shared.global [%0], [%1], 16;" :: "r"(s), "l"(g) : "memory")
#define CP_COMMIT() asm volatile("cp.async.commit_group;" ::: "memory")

// ------------------------- prep -------------------------
__global__ void init_kernel() {
    int i = threadIdx.x;
    if (i == 0) g_ticket = 0;
    if (i < NTILE) g_done[i] = 0;
    for (int j = i + NTILE; j < NTILE; j += blockDim.x) g_done[j] = 0;
}

__global__ void transpose_cb_kernel(const float* __restrict__ cb) {
    __shared__ float tile[32][33];
    int s = blockIdx.z;
    int d0 = blockIdx.x * 32, c0 = blockIdx.y * 32;
    int tx = threadIdx.x, ty = threadIdx.y;
    const float* src = cb + (size_t)s * CDSZ * DDIM;
    float* dst = g_cbT + (size_t)s * DDIM * CDSZ;
#pragma unroll
    for (int i = 0; i < 32; i += 8)
        tile[ty + i][tx] = src[(size_t)(c0 + ty + i) * DDIM + d0 + tx];
    __syncthreads();
#pragma unroll
    for (int i = 0; i < 32; i += 8)
        dst[(size_t)(d0 + ty + i) * CDSZ + c0 + tx] = tile[tx][ty + i];
}

__global__ void cnorm_kernel(const float* __restrict__ cb) {
    int row = blockIdx.x * 8 + (threadIdx.x >> 5);
    int lane = threadIdx.x & 31;
    const float* p = cb + (size_t)row * DDIM;
    float s = 0.f;
#pragma unroll
    for (int j = 0; j < 8; j++) { float v = p[lane + 32 * j]; s = fmaf(v, v, s); }
#pragma unroll
    for (int off = 16; off; off >>= 1) s += __shfl_xor_sync(0xffffffffu, s, off);
    if (lane == 0) g_cnorm[row] = s;
}

// ------------------------- persistent (stage,tile) pipeline -------------------------
extern __shared__ float smem_dyn[];

__global__ __launch_bounds__(128, 2) void rvq_persist_kernel(
    const float* __restrict__ x,
    const float* __restrict__ cball,   // codebooks [K][CDSZ][DDIM] c-major
    float* __restrict__ encf)          // d_out + 2
{
    float* As = smem_dyn;                                   // [TM][AS_STRIDE]
    float4* Bs4 = (float4*)(smem_dyn + TM * AS_STRIDE);     // 2 x [16k][4q][16]
    __shared__ float rnorm_s[TM];
    __shared__ int bestI_s[TM];
    __shared__ float wsum[4];
    __shared__ int s_ticket;

    const int tid = threadIdx.x;
    const int tx = tid & 15, ty = tid >> 4;
    const uint32_t sB = smem_u32(Bs4);

    while (true) {
        if (tid == 0) s_ticket = atomicAdd(&g_ticket, 1);
        __syncthreads();
        const int ticket = s_ticket;
        __syncthreads();
        if (ticket >= NUNITS) break;
        const int stage = ticket >> 9;          // stage-major order
        const int tile = ticket & (NTILE - 1);
        const int tok0 = tile * TM;
        const float* cbT = g_cbT + (size_t)stage * DDIM * CDSZ;
        const float* cnorm = g_cnorm + stage * CDSZ;
        const float* cb = cball + (size_t)stage * CDSZ * DDIM;

        // wait for (stage-1, tile)
        if (stage > 0 && tid == 0) {
            while (ld_acquire(&g_done[tile]) < stage) __nanosleep(100);
        }
        __syncthreads();

        // load 64x256 residual tile; g_res via L2 (bypass possibly-stale L1)
        if (stage == 0) {
#pragma unroll
            for (int it = 0; it < 32; it++) {
                int idx4 = it * 128 + tid;
                int r = idx4 >> 6, c4 = (idx4 & 63) << 2;
                float4 v = *(const float4*)&x[(size_t)(tok0 + r) * DDIM + c4];
                *(float4*)&As[r * AS_STRIDE + c4] = v;
            }
        } else {
#pragma unroll
            for (int it = 0; it < 32; it++) {
                int idx4 = it * 128 + tid;
                int r = idx4 >> 6, c4 = (idx4 & 63) << 2;
                float4 v = __ldcg((const float4*)&g_res[(size_t)(tok0 + r) * DDIM + c4]);
                *(float4*)&As[r * AS_STRIDE + c4] = v;
            }
        }
        __syncthreads();

        // rnorm per token (bit-exact chain)
        {
            const int warpId = tid >> 5, lane = tid & 31;
            for (int t = warpId; t < TM; t += 4) {
                float s = 0.f;
#pragma unroll
                for (int j = 0; j < 8; j++) {
                    float v = As[t * AS_STRIDE + lane + 32 * j];
                    s = fmaf(v, v, s);
                }
#pragma unroll
                for (int off = 16; off; off >>= 1) s += __shfl_xor_sync(0xffffffffu, s, off);
                if (lane == 0) rnorm_s[t] = s;
            }
        }

        float bestVr[8];
        int bestIr[8];
#pragma unroll
        for (int i = 0; i < 8; i++) { bestVr[i] = 3.4e38f; bestIr[i] = 0; }

        for (int ct = 0; ct < CDSZ; ct += TN) {
            u64 acc[8][8];
#pragma unroll
            for (int i = 0; i < 8; i++)
#pragma unroll
                for (int j = 0; j < 8; j++) acc[i][j] = 0ull;

            // prime slice 0 -> buf0  (prev chunk's last sync guarantees buf0 free)
            __syncthreads();
#pragma unroll
            for (int it = 0; it < 8; it++) {
                int g = it * 128 + tid;
                int k = g >> 6, rem = g & 63;
                int txg = rem >> 2, q = rem & 3;
                uint32_t dst = sB + (uint32_t)(((k * 4 + q) * 16 + ((txg + 4 * q) & 15)) * 16);
                CP_ASYNC16(dst, &cbT[(size_t)k * CDSZ + ct + rem * 4]);
            }
            CP_COMMIT();

            for (int sl = 0; sl < DDIM / TKC; sl++) {
                if (sl < DDIM / TKC - 1) {
                    int kk = (sl + 1) * TKC;
                    uint32_t bufo = sB + (uint32_t)(((sl + 1) & 1) * BS_F4 * 16);
#pragma unroll
                    for (int it = 0; it < 8; it++) {
                        int g = it * 128 + tid;
                        int k = g >> 6, rem = g & 63;
                        int txg = rem >> 2, q = rem & 3;
                        uint32_t dst = bufo + (uint32_t)(((k * 4 + q) * 16 + ((txg + 4 * q) & 15)) * 16);
                        CP_ASYNC16(dst, &cbT[(size_t)(kk + k) * CDSZ + ct + rem * 4]);
                    }
                    CP_COMMIT();
                    asm volatile("cp.async.wait_group 1;" ::: "memory");
                } else {
                    asm volatile("cp.async.wait_group 0;" ::: "memory");
                }
                __syncthreads();   // buffer sl&1 visible to all

                const float4* Bcur = Bs4 + (sl & 1) * BS_F4;
                const int kk = sl * TKC;
#pragma unroll
                for (int k4 = 0; k4 < TKC; k4 += 4) {
                    float4 a4[8];
#pragma unroll
                    for (int i = 0; i < 8; i++)
                        a4[i] = *(const float4*)&As[(ty * 8 + i) * AS_STRIDE + kk + k4];
#pragma unroll
                    for (int dk = 0; dk < 4; dk++) {
                        const ulonglong2* bp = (const ulonglong2*)(Bcur + (k4 + dk) * 64);
                        ulonglong2 B0 = bp[tx];
                        ulonglong2 B1 = bp[16 + ((tx + 4) & 15)];
                        ulonglong2 B2 = bp[32 + ((tx + 8) & 15)];
                        ulonglong2 B3 = bp[48 + ((tx + 12) & 15)];
#pragma unroll
                        for (int i = 0; i < 8; i++) {
                            float av = ((const float*)&a4[i])[dk];
                            u64 ap = pack2(av, av);
                            acc[i][0] = fma2(ap, B0.x, acc[i][0]);
                            acc[i][1] = fma2(ap, B0.y, acc[i][1]);
                            acc[i][2] = fma2(ap, B1.x, acc[i][2]);
                            acc[i][3] = fma2(ap, B1.y, acc[i][3]);
                            acc[i][4] = fma2(ap, B2.x, acc[i][4]);
                            acc[i][5] = fma2(ap, B2.y, acc[i][5]);
                            acc[i][6] = fma2(ap, B3.x, acc[i][6]);
                            acc[i][7] = fma2(ap, B3.y, acc[i][7]);
                        }
                    }
                }
                __syncthreads();   // readers done with buffer sl&1 (safe to refill at sl+2)
            }

            // d2 combine + argmin (identical chain)
            float2 cnp[8];
#pragma unroll
            for (int j = 0; j < 8; j++)
                cnp[j] = *(const float2*)&cnorm[ct + tx * 16 + j * 2];

#pragma unroll
            for (int i = 0; i < 8; i++) {
                float R = rnorm_s[ty * 8 + i];
                float bv = 3.4e38f; int bi = 0;
#pragma unroll
                for (int j = 0; j < 8; j++) {
                    float2 f = unpack2(acc[i][j]);
                    int c0 = ct + tx * 16 + j * 2;
                    float d2x = __fadd_rn(__fsub_rn(R, __fmul_rn(2.0f, f.x)), cnp[j].x);
                    float d2y = __fadd_rn(__fsub_rn(R, __fmul_rn(2.0f, f.y)), cnp[j].y);
                    if (d2x < bv) { bv = d2x; bi = c0; }
                    if (d2y < bv) { bv = d2y; bi = c0 + 1; }
                }
#pragma unroll
                for (int off = 8; off; off >>= 1) {
                    float ov = __shfl_xor_sync(0xffffffffu, bv, off);
                    int oi = __shfl_xor_sync(0xffffffffu, bi, off);
                    if (ov < bv || (ov == bv && oi < bi)) { bv = ov; bi = oi; }
                }
                if (bv < bestVr[i]) { bestVr[i] = bv; bestIr[i] = bi; }
            }
        }
        if (tx == 0) {
#pragma unroll
            for (int i = 0; i < 8; i++) bestI_s[ty * 8 + i] = bestIr[i];
        }
        __syncthreads();

        // residual update + loss partial + enc out
        const int warpId = tid >> 5, lane = tid & 31;
        float lsum = 0.f;
        for (int t = warpId; t < TM; t += 4) {
            int token = tok0 + t;
            int e = bestI_s[t];
            const float* crow = cb + (size_t)e * DDIM;
#pragma unroll
            for (int jj = 0; jj < 8; jj++) {
                int d = lane + jj * 32;
                float r = As[t * AS_STRIDE + d];
                float c = __ldg(&crow[d]);
                float nr = r - c;
                g_res[(size_t)token * DDIM + d] = nr;
                lsum = fmaf(nr, nr, lsum);
            }
            if (lane == 0) encf[(size_t)token * KSTAGES + stage] = (float)e;
        }
#pragma unroll
        for (int off = 16; off; off >>= 1) lsum += __shfl_xor_sync(0xffffffffu, lsum, off);
        if (lane == 0) wsum[warpId] = lsum;
        __syncthreads();
        if (tid == 0) {
            g_partials[stage * NTILE + tile] = wsum[0] + wsum[1] + wsum[2] + wsum[3];
            __threadfence();
            st_release(&g_done[tile], stage + 1);
        }
        // next ticket (loop top has syncthreads)
    }
}

// ------------------------- epilogue -------------------------
__global__ void finalize_kernel(float* __restrict__ out) {
    __shared__ float sh[256];
    int tid = threadIdx.x;
    float s = 0.f;
    for (int i = tid; i < NUNITS; i += 256) s += g_partials[i];
    sh[tid] = s;
    __syncthreads();
    for (int off = 128; off; off >>= 1) {
        if (tid < off) sh[tid] += sh[tid + off];
        __syncthreads();
    }
    if (tid == 0) {
        float loss = sh[0] * (1.0f / (float)((size_t)N_TOK * DDIM));
        out[0] = loss;
        out[1] = loss;
    }
}

__global__ void quant_kernel(const float* __restrict__ x, float* __restrict__ out) {
    float* q = out + 2 + (size_t)N_TOK * KSTAGES;
    int i = blockIdx.x * blockDim.x + threadIdx.x;
    int stride = gridDim.x * blockDim.x;
    for (; i < N_TOK * DDIM; i += stride) q[i] = x[i] - g_res[i];
}

// ------------------------- launch -------------------------
extern "C" void kernel_launch(void* const* d_in, const int* in_sizes, int n_in,
                              void* d_out, int out_size) {
    const float* x  = (const float*)d_in[0];
    const float* cb = (const float*)d_in[1];
    if (n_in >= 2 && in_sizes[0] == KSTAGES * CDSZ * DDIM && in_sizes[1] == N_TOK * DDIM) {
        const float* t = x; x = cb; cb = t;
    }
    float* out = (float*)d_out;

    cudaFuncSetAttribute(rvq_persist_kernel,
                         cudaFuncAttributeMaxDynamicSharedMemorySize, SMEM_BYTES);

    init_kernel<<<1, 512>>>();
    transpose_cb_kernel<<<dim3(8, 32, 8), dim3(32, 8)>>>(cb);
    cnorm_kernel<<<(KSTAGES * CDSZ) / 8, 256>>>(cb);

    rvq_persist_kernel<<<GRID_P, 128, SMEM_BYTES>>>(x, cb, out + 2);

    finalize_kernel<<<1, 256>>>(out);
    quant_kernel<<<4096, 256>>>(x, out);
}